// round 15
// baseline (speedup 1.0000x reference)
#include <cuda_runtime.h>
#include <cuda_bf16.h>
#include <cstdint>

#define N_NODES 100000
#define D_IN    500
#define D_H     128
#define D_O     64
#define E_MAX   3200000
#define NB1     ((N_NODES + 255) / 256)

// ---------------- scratch ----------------
__device__ int   g_cnt [N_NODES];
__device__ float g_dinv[N_NODES];
__device__ int   g_off [N_NODES];
__device__ int   g_cur [N_NODES];
__device__ int   g_part[512];
__device__ int2  g_cse [E_MAX];   // (src, eid) per in-edge, grouped by dst
// W^T bf16 hi/lo pre-packed in mma.m16n8k16 B-fragment order
__device__ __align__(16) uint32_t g_bhi[32 * 1024];   // W1
__device__ __align__(16) uint32_t g_blo[32 * 1024];
__device__ __align__(16) uint32_t g_b2hi[8 * 512];    // W2
__device__ __align__(16) uint32_t g_b2lo[8 * 512];
__device__ float g_hs  [(size_t)N_NODES * D_H];
__device__ float g_acc1[(size_t)N_NODES * D_H];
__device__ float g_hs2 [(size_t)N_NODES * D_O];
__device__ float g_z   [(size_t)N_NODES * D_O];

__device__ __forceinline__ uint32_t smem_u32(const void* p) {
    uint32_t a;
    asm("{ .reg .u64 t; cvta.to.shared.u64 t, %1; cvt.u32.u64 %0, t; }"
        : "=r"(a) : "l"(p));
    return a;
}

// ---------------- degree / CSR ----------------
__global__ void cnt_init_kernel() {
    int i = blockIdx.x * blockDim.x + threadIdx.x;
    if (i < N_NODES) g_cnt[i] = 0;
}
__global__ void deg_count_kernel(const int* __restrict__ col, int E) {
    int e = blockIdx.x * blockDim.x + threadIdx.x;
    if (e < E) atomicAdd(&g_cnt[col[e]], 1);
}
__global__ void scan1_kernel() {   // + dinv fused
    __shared__ int s[256];
    int tid = threadIdx.x;
    int i = blockIdx.x * 256 + tid;
    int v = (i < N_NODES) ? g_cnt[i] : 0;
    if (i < N_NODES) g_dinv[i] = rsqrtf((float)(v + 1));
    s[tid] = v;
    __syncthreads();
    #pragma unroll
    for (int d = 1; d < 256; d <<= 1) {
        int t = (tid >= d) ? s[tid - d] : 0;
        __syncthreads();
        s[tid] += t;
        __syncthreads();
    }
    if (i < N_NODES) g_off[i] = s[tid] - v;
    if (tid == 255) g_part[blockIdx.x] = s[255];
}
__global__ void scan2_kernel() {
    __shared__ int s[512];
    int tid = threadIdx.x;
    int v = (tid < NB1) ? g_part[tid] : 0;
    s[tid] = v;
    __syncthreads();
    #pragma unroll
    for (int d = 1; d < 512; d <<= 1) {
        int t = (tid >= d) ? s[tid - d] : 0;
        __syncthreads();
        s[tid] += t;
        __syncthreads();
    }
    if (tid < NB1) g_part[tid] = s[tid] - v;
}
__global__ void scan3b_kernel() {
    int i = blockIdx.x * blockDim.x + threadIdx.x;
    if (i < N_NODES) {
        g_off[i] += g_part[i >> 8];
        g_cur[i] = 0;
    }
}
__global__ void csr_fill_kernel(const int* __restrict__ ei, int E) {
    int e = blockIdx.x * blockDim.x + threadIdx.x;
    if (e >= E) return;
    int r = ei[e];
    int c = ei[E + e];
    int pos = g_off[c] + atomicAdd(&g_cur[c], 1);
    g_cse[pos] = make_int2(r, e);
}

// ---------------- fused W1+W2 split into mma B fragments -------------------
__global__ void wsplit_kernel(const float* __restrict__ W1,
                              const float* __restrict__ W2) {
    int i = blockIdx.x * blockDim.x + threadIdx.x;
    if (i < 32768) {
        int reg   = i & 1;
        int lane  = (i >> 1) & 31;
        int ntile = (i >> 6) & 15;
        int kstep = i >> 10;
        int n = ntile * 8 + (lane >> 2);
        int k = kstep * 16 + reg * 8 + (lane & 3) * 2;
        float w0 = (k     < D_IN) ? W1[(size_t)k * D_H + n]       : 0.0f;
        float w1 = (k + 1 < D_IN) ? W1[(size_t)(k + 1) * D_H + n] : 0.0f;
        __nv_bfloat16 h0 = __float2bfloat16(w0);
        __nv_bfloat16 h1 = __float2bfloat16(w1);
        __nv_bfloat16 l0 = __float2bfloat16(w0 - __bfloat162float(h0));
        __nv_bfloat16 l1 = __float2bfloat16(w1 - __bfloat162float(h1));
        __nv_bfloat162 hp = {h0, h1}, lp = {l0, l1};
        int idx = kstep * 1024 + (ntile >> 1) * 128 + lane * 4 + (ntile & 1) * 2 + reg;
        g_bhi[idx] = *(uint32_t*)&hp;
        g_blo[idx] = *(uint32_t*)&lp;
    } else if (i < 32768 + 4096) {
        int j = i - 32768;
        int reg   = j & 1;
        int lane  = (j >> 1) & 31;
        int ntile = (j >> 6) & 7;
        int kstep = j >> 9;
        int n = ntile * 8 + (lane >> 2);
        int k = kstep * 16 + reg * 8 + (lane & 3) * 2;
        float w0 = W2[(size_t)k * D_O + n];
        float w1 = W2[(size_t)(k + 1) * D_O + n];
        __nv_bfloat16 h0 = __float2bfloat16(w0);
        __nv_bfloat16 h1 = __float2bfloat16(w1);
        __nv_bfloat16 l0 = __float2bfloat16(w0 - __bfloat162float(h0));
        __nv_bfloat16 l1 = __float2bfloat16(w1 - __bfloat162float(h1));
        __nv_bfloat162 hp = {h0, h1}, lp = {l0, l1};
        int idx = kstep * 512 + (ntile >> 1) * 128 + lane * 4 + (ntile & 1) * 2 + reg;
        g_b2hi[idx] = *(uint32_t*)&hp;
        g_b2lo[idx] = *(uint32_t*)&lp;
    }
}

// ---------------- GEMM1: BM=256, 16 warps, 512 threads ---------------------
__global__ void __launch_bounds__(512) gemm1_mma_kernel(const float* __restrict__ X) {
    extern __shared__ __align__(16) uint8_t sm[];
    uint8_t* Ahi = sm;                // 256 rows x 128B = 32KB
    uint8_t* Alo = sm + 32768;        // 32KB

    const int tid  = threadIdx.x;
    const int wid  = tid >> 5;
    const int lane = tid & 31;
    const int m0   = blockIdx.x * 256;
    const int warp_m = (wid >> 1) * 32;
    const int warp_n = (wid & 1) * 64;

    const uint32_t ahi_base = smem_u32(Ahi);
    const uint32_t alo_base = smem_u32(Alo);

    const int arow  = tid >> 1;
    const int ahalf = tid & 1;
    const int gm    = m0 + arow;
    const float* xrow = X + (size_t)gm * D_IN;
    const bool rok = (gm < N_NODES);

    float acc[2][8][4];
    #pragma unroll
    for (int mt = 0; mt < 2; mt++)
        #pragma unroll
        for (int nt = 0; nt < 8; nt++)
            #pragma unroll
            for (int r = 0; r < 4; r++) acc[mt][nt][r] = 0.0f;

    for (int chunk = 0; chunk < 8; chunk++) {
        if (chunk > 0) __syncthreads();
        #pragma unroll
        for (int q = 0; q < 8; q++) {
            int kl = ahalf * 32 + q * 4;
            int kg = chunk * 64 + kl;
            float4 v = make_float4(0.f, 0.f, 0.f, 0.f);
            if (rok && kg < D_IN) v = *(const float4*)(xrow + kg);
            __nv_bfloat16 h0 = __float2bfloat16(v.x);
            __nv_bfloat16 h1 = __float2bfloat16(v.y);
            __nv_bfloat16 h2 = __float2bfloat16(v.z);
            __nv_bfloat16 h3 = __float2bfloat16(v.w);
            __nv_bfloat16 l0 = __float2bfloat16(v.x - __bfloat162float(h0));
            __nv_bfloat16 l1 = __float2bfloat16(v.y - __bfloat162float(h1));
            __nv_bfloat16 l2 = __float2bfloat16(v.z - __bfloat162float(h2));
            __nv_bfloat16 l3 = __float2bfloat16(v.w - __bfloat162float(h3));
            int ch  = kl >> 3;
            int sub = (kl & 7) ? 8 : 0;
            uint32_t off = arow * 128 + ((ch ^ (arow & 7)) << 4) + sub;
            __nv_bfloat162 hp0 = {h0, h1}, hp1 = {h2, h3};
            __nv_bfloat162 lp0 = {l0, l1}, lp1 = {l2, l3};
            uint2 hv = { *(uint32_t*)&hp0, *(uint32_t*)&hp1 };
            uint2 lv = { *(uint32_t*)&lp0, *(uint32_t*)&lp1 };
            *(uint2*)(Ahi + off) = hv;
            *(uint2*)(Alo + off) = lv;
        }
        __syncthreads();

        #pragma unroll
        for (int kstep = 0; kstep < 4; kstep++) {
            int kg = chunk * 4 + kstep;
            uint32_t ah[2][4], al[2][4];
            #pragma unroll
            for (int mt = 0; mt < 2; mt++) {
                int mrow = warp_m + mt * 16 + (lane & 7) + ((lane & 8) ? 8 : 0);
                int ch   = kstep * 2 + (lane >> 4);
                uint32_t off = mrow * 128 + ((ch ^ (mrow & 7)) << 4);
                asm volatile("ldmatrix.sync.aligned.m8n8.x4.shared.b16 {%0,%1,%2,%3}, [%4];"
                             : "=r"(ah[mt][0]), "=r"(ah[mt][1]), "=r"(ah[mt][2]), "=r"(ah[mt][3])
                             : "r"(ahi_base + off));
                asm volatile("ldmatrix.sync.aligned.m8n8.x4.shared.b16 {%0,%1,%2,%3}, [%4];"
                             : "=r"(al[mt][0]), "=r"(al[mt][1]), "=r"(al[mt][2]), "=r"(al[mt][3])
                             : "r"(alo_base + off));
            }
            uint4 bh[4], bl[4];
            #pragma unroll
            for (int p = 0; p < 4; p++) {
                int npair = (warp_n >> 4) + p;
                int idx = kg * 1024 + npair * 128 + lane * 4;
                bh[p] = *(const uint4*)(g_bhi + idx);
                bl[p] = *(const uint4*)(g_blo + idx);
            }
            #pragma unroll
            for (int mt = 0; mt < 2; mt++) {
                #pragma unroll
                for (int nt = 0; nt < 8; nt++) {
                    int p = nt >> 1;
                    uint32_t bh0 = (nt & 1) ? bh[p].z : bh[p].x;
                    uint32_t bh1 = (nt & 1) ? bh[p].w : bh[p].y;
                    uint32_t bl0 = (nt & 1) ? bl[p].z : bl[p].x;
                    uint32_t bl1 = (nt & 1) ? bl[p].w : bl[p].y;
                    float* c = acc[mt][nt];
                    asm volatile("mma.sync.aligned.m16n8k16.row.col.f32.bf16.bf16.f32 "
                        "{%0,%1,%2,%3}, {%4,%5,%6,%7}, {%8,%9}, {%0,%1,%2,%3};"
                        : "+f"(c[0]), "+f"(c[1]), "+f"(c[2]), "+f"(c[3])
                        : "r"(ah[mt][0]), "r"(ah[mt][1]), "r"(ah[mt][2]), "r"(ah[mt][3]),
                          "r"(bh0), "r"(bh1));
                    asm volatile("mma.sync.aligned.m16n8k16.row.col.f32.bf16.bf16.f32 "
                        "{%0,%1,%2,%3}, {%4,%5,%6,%7}, {%8,%9}, {%0,%1,%2,%3};"
                        : "+f"(c[0]), "+f"(c[1]), "+f"(c[2]), "+f"(c[3])
                        : "r"(ah[mt][0]), "r"(ah[mt][1]), "r"(ah[mt][2]), "r"(ah[mt][3]),
                          "r"(bl0), "r"(bl1));
                    asm volatile("mma.sync.aligned.m16n8k16.row.col.f32.bf16.bf16.f32 "
                        "{%0,%1,%2,%3}, {%4,%5,%6,%7}, {%8,%9}, {%0,%1,%2,%3};"
                        : "+f"(c[0]), "+f"(c[1]), "+f"(c[2]), "+f"(c[3])
                        : "r"(al[mt][0]), "r"(al[mt][1]), "r"(al[mt][2]), "r"(al[mt][3]),
                          "r"(bh0), "r"(bh1));
                }
            }
        }
    }

    #pragma unroll
    for (int mt = 0; mt < 2; mt++) {
        int r0 = m0 + warp_m + mt * 16 + (lane >> 2);
        int r1 = r0 + 8;
        float d0 = (r0 < N_NODES) ? g_dinv[r0] : 0.0f;
        float d1 = (r1 < N_NODES) ? g_dinv[r1] : 0.0f;
        #pragma unroll
        for (int nt = 0; nt < 8; nt++) {
            int cc = warp_n + nt * 8 + (lane & 3) * 2;
            if (r0 < N_NODES) {
                float2 o = make_float2(acc[mt][nt][0] * d0, acc[mt][nt][1] * d0);
                *(float2*)&g_hs[(size_t)r0 * D_H + cc] = o;
            }
            if (r1 < N_NODES) {
                float2 o = make_float2(acc[mt][nt][2] * d1, acc[mt][nt][3] * d1);
                *(float2*)&g_hs[(size_t)r1 * D_H + cc] = o;
            }
        }
    }
}

// ---------------- agg1: CSR gather, warp per node, float4 lanes ------------
__global__ void __launch_bounds__(256) agg1_kernel() {
    int w = (blockIdx.x * blockDim.x + threadIdx.x) >> 5;
    int lane = threadIdx.x & 31;
    if (w >= N_NODES) return;
    int start = g_off[w];
    int cnt   = g_cnt[w];
    const float* base = &g_hs[(size_t)lane * 4];
    float4 acc = *(const float4*)&g_hs[(size_t)w * D_H + lane * 4];

    for (int b = 0; b < cnt; b += 32) {
        int n = min(32, cnt - b);
        int src = (lane < n) ? g_cse[start + b + lane].x : 0;
        int j = 0;
        for (; j + 4 <= n; j += 4) {
            int s0 = __shfl_sync(0xffffffffu, src, j);
            int s1 = __shfl_sync(0xffffffffu, src, j + 1);
            int s2 = __shfl_sync(0xffffffffu, src, j + 2);
            int s3 = __shfl_sync(0xffffffffu, src, j + 3);
            float4 v0 = *(const float4*)(base + (size_t)s0 * D_H);
            float4 v1 = *(const float4*)(base + (size_t)s1 * D_H);
            float4 v2 = *(const float4*)(base + (size_t)s2 * D_H);
            float4 v3 = *(const float4*)(base + (size_t)s3 * D_H);
            acc.x += (v0.x + v1.x) + (v2.x + v3.x);
            acc.y += (v0.y + v1.y) + (v2.y + v3.y);
            acc.z += (v0.z + v1.z) + (v2.z + v3.z);
            acc.w += (v0.w + v1.w) + (v2.w + v3.w);
        }
        for (; j < n; j++) {
            int s = __shfl_sync(0xffffffffu, src, j);
            float4 v = *(const float4*)(base + (size_t)s * D_H);
            acc.x += v.x; acc.y += v.y; acc.z += v.z; acc.w += v.w;
        }
    }
    *(float4*)&g_acc1[(size_t)w * D_H + lane * 4] = acc;
}

// ---------------- GEMM2: BM=256, 16 warps, 512 threads ---------------------
__global__ void __launch_bounds__(512) gemm2_mma_kernel(const float* __restrict__ b1) {
    extern __shared__ __align__(16) uint8_t sm[];
    uint8_t* Ahi = sm;                // 256 rows x 128B = 32KB
    uint8_t* Alo = sm + 32768;

    const int tid  = threadIdx.x;
    const int wid  = tid >> 5;
    const int lane = tid & 31;
    const int m0   = blockIdx.x * 256;
    const int warp_m = (wid >> 1) * 32;   // 8 M-warps over 256 rows
    const int warp_n = (wid & 1) * 32;    // 2 N-warps over 64 cols

    const uint32_t ahi_base = smem_u32(Ahi);
    const uint32_t alo_base = smem_u32(Alo);

    const int arow  = tid >> 1;           // 0..255
    const int ahalf = tid & 1;
    const int gm    = m0 + arow;
    const bool rok = (gm < N_NODES);
    const float dA = rok ? g_dinv[gm] : 0.0f;
    const float* arowp = g_acc1 + (size_t)gm * D_H;

    float acc[2][4][4];
    #pragma unroll
    for (int mt = 0; mt < 2; mt++)
        #pragma unroll
        for (int nt = 0; nt < 4; nt++)
            #pragma unroll
            for (int r = 0; r < 4; r++) acc[mt][nt][r] = 0.0f;

    for (int chunk = 0; chunk < 2; chunk++) {
        if (chunk > 0) __syncthreads();
        #pragma unroll
        for (int q = 0; q < 8; q++) {
            int kl = ahalf * 32 + q * 4;
            int kg = chunk * 64 + kl;
            float4 v = make_float4(0.f, 0.f, 0.f, 0.f);
            if (rok) {
                float4 a = *(const float4*)(arowp + kg);
                float4 bb = *(const float4*)(b1 + kg);
                v.x = fmaxf(fmaf(a.x, dA, bb.x), 0.0f);
                v.y = fmaxf(fmaf(a.y, dA, bb.y), 0.0f);
                v.z = fmaxf(fmaf(a.z, dA, bb.z), 0.0f);
                v.w = fmaxf(fmaf(a.w, dA, bb.w), 0.0f);
            }
            __nv_bfloat16 h0 = __float2bfloat16(v.x);
            __nv_bfloat16 h1 = __float2bfloat16(v.y);
            __nv_bfloat16 h2 = __float2bfloat16(v.z);
            __nv_bfloat16 h3 = __float2bfloat16(v.w);
            __nv_bfloat16 l0 = __float2bfloat16(v.x - __bfloat162float(h0));
            __nv_bfloat16 l1 = __float2bfloat16(v.y - __bfloat162float(h1));
            __nv_bfloat16 l2 = __float2bfloat16(v.z - __bfloat162float(h2));
            __nv_bfloat16 l3 = __float2bfloat16(v.w - __bfloat162float(h3));
            int ch  = kl >> 3;
            int sub = (kl & 7) ? 8 : 0;
            uint32_t off = arow * 128 + ((ch ^ (arow & 7)) << 4) + sub;
            __nv_bfloat162 hp0 = {h0, h1}, hp1 = {h2, h3};
            __nv_bfloat162 lp0 = {l0, l1}, lp1 = {l2, l3};
            uint2 hv = { *(uint32_t*)&hp0, *(uint32_t*)&hp1 };
            uint2 lv = { *(uint32_t*)&lp0, *(uint32_t*)&lp1 };
            *(uint2*)(Ahi + off) = hv;
            *(uint2*)(Alo + off) = lv;
        }
        __syncthreads();

        #pragma unroll
        for (int kstep = 0; kstep < 4; kstep++) {
            int kg = chunk * 4 + kstep;
            uint32_t ah[2][4], al[2][4];
            #pragma unroll
            for (int mt = 0; mt < 2; mt++) {
                int mrow = warp_m + mt * 16 + (lane & 15);
                int ch   = kstep * 2 + (lane >> 4);
                uint32_t off = mrow * 128 + ((ch ^ (mrow & 7)) << 4);
                asm volatile("ldmatrix.sync.aligned.m8n8.x4.shared.b16 {%0,%1,%2,%3}, [%4];"
                             : "=r"(ah[mt][0]), "=r"(ah[mt][1]), "=r"(ah[mt][2]), "=r"(ah[mt][3])
                             : "r"(ahi_base + off));
                asm volatile("ldmatrix.sync.aligned.m8n8.x4.shared.b16 {%0,%1,%2,%3}, [%4];"
                             : "=r"(al[mt][0]), "=r"(al[mt][1]), "=r"(al[mt][2]), "=r"(al[mt][3])
                             : "r"(alo_base + off));
            }
            uint4 bh[2], bl[2];
            #pragma unroll
            for (int p = 0; p < 2; p++) {
                int npair = (warp_n >> 4) + p;
                int idx = kg * 512 + npair * 128 + lane * 4;
                bh[p] = *(const uint4*)(g_b2hi + idx);
                bl[p] = *(const uint4*)(g_b2lo + idx);
            }
            #pragma unroll
            for (int mt = 0; mt < 2; mt++) {
                #pragma unroll
                for (int nt = 0; nt < 4; nt++) {
                    int p = nt >> 1;
                    uint32_t bh0 = (nt & 1) ? bh[p].z : bh[p].x;
                    uint32_t bh1 = (nt & 1) ? bh[p].w : bh[p].y;
                    uint32_t bl0 = (nt & 1) ? bl[p].z : bl[p].x;
                    uint32_t bl1 = (nt & 1) ? bl[p].w : bl[p].y;
                    float* c = acc[mt][nt];
                    asm volatile("mma.sync.aligned.m16n8k16.row.col.f32.bf16.bf16.f32 "
                        "{%0,%1,%2,%3}, {%4,%5,%6,%7}, {%8,%9}, {%0,%1,%2,%3};"
                        : "+f"(c[0]), "+f"(c[1]), "+f"(c[2]), "+f"(c[3])
                        : "r"(ah[mt][0]), "r"(ah[mt][1]), "r"(ah[mt][2]), "r"(ah[mt][3]),
                          "r"(bh0), "r"(bh1));
                    asm volatile("mma.sync.aligned.m16n8k16.row.col.f32.bf16.bf16.f32 "
                        "{%0,%1,%2,%3}, {%4,%5,%6,%7}, {%8,%9}, {%0,%1,%2,%3};"
                        : "+f"(c[0]), "+f"(c[1]), "+f"(c[2]), "+f"(c[3])
                        : "r"(ah[mt][0]), "r"(ah[mt][1]), "r"(ah[mt][2]), "r"(ah[mt][3]),
                          "r"(bl0), "r"(bl1));
                    asm volatile("mma.sync.aligned.m16n8k16.row.col.f32.bf16.bf16.f32 "
                        "{%0,%1,%2,%3}, {%4,%5,%6,%7}, {%8,%9}, {%0,%1,%2,%3};"
                        : "+f"(c[0]), "+f"(c[1]), "+f"(c[2]), "+f"(c[3])
                        : "r"(al[mt][0]), "r"(al[mt][1]), "r"(al[mt][2]), "r"(al[mt][3]),
                          "r"(bh0), "r"(bh1));
                }
            }
        }
    }

    #pragma unroll
    for (int mt = 0; mt < 2; mt++) {
        int r0 = m0 + warp_m + mt * 16 + (lane >> 2);
        int r1 = r0 + 8;
        float d0 = (r0 < N_NODES) ? g_dinv[r0] : 0.0f;
        float d1 = (r1 < N_NODES) ? g_dinv[r1] : 0.0f;
        #pragma unroll
        for (int nt = 0; nt < 4; nt++) {
            int cc = warp_n + nt * 8 + (lane & 3) * 2;
            if (r0 < N_NODES) {
                float2 o = make_float2(acc[mt][nt][0] * d0, acc[mt][nt][1] * d0);
                *(float2*)&g_hs2[(size_t)r0 * D_O + cc] = o;
            }
            if (r1 < N_NODES) {
                float2 o = make_float2(acc[mt][nt][2] * d1, acc[mt][nt][3] * d1);
                *(float2*)&g_hs2[(size_t)r1 * D_O + cc] = o;
            }
        }
    }
}

// ---------------- agg2: CSR gather, warp per node, float2 lanes ------------
__global__ void __launch_bounds__(256) agg2_kernel(const float* __restrict__ b2) {
    int w = (blockIdx.x * blockDim.x + threadIdx.x) >> 5;
    int lane = threadIdx.x & 31;
    if (w >= N_NODES) return;
    int start = g_off[w];
    int cnt   = g_cnt[w];
    const float* base = &g_hs2[(size_t)lane * 2];
    float2 acc = *(const float2*)&g_hs2[(size_t)w * D_O + lane * 2];

    for (int b = 0; b < cnt; b += 32) {
        int n = min(32, cnt - b);
        int src = (lane < n) ? g_cse[start + b + lane].x : 0;
        int j = 0;
        for (; j + 4 <= n; j += 4) {
            int s0 = __shfl_sync(0xffffffffu, src, j);
            int s1 = __shfl_sync(0xffffffffu, src, j + 1);
            int s2 = __shfl_sync(0xffffffffu, src, j + 2);
            int s3 = __shfl_sync(0xffffffffu, src, j + 3);
            float2 v0 = *(const float2*)(base + (size_t)s0 * D_O);
            float2 v1 = *(const float2*)(base + (size_t)s1 * D_O);
            float2 v2 = *(const float2*)(base + (size_t)s2 * D_O);
            float2 v3 = *(const float2*)(base + (size_t)s3 * D_O);
            acc.x += (v0.x + v1.x) + (v2.x + v3.x);
            acc.y += (v0.y + v1.y) + (v2.y + v3.y);
        }
        for (; j < n; j++) {
            int s = __shfl_sync(0xffffffffu, src, j);
            float2 v = *(const float2*)(base + (size_t)s * D_O);
            acc.x += v.x; acc.y += v.y;
        }
    }
    float d = g_dinv[w];
    float2 z = make_float2(fmaf(acc.x, d, b2[lane * 2]),
                           fmaf(acc.y, d, b2[lane * 2 + 1]));
    *(float2*)&g_z[(size_t)w * D_O + lane * 2] = z;
}

// ---------------- decode (CSR order): warp per dst node -------------------
__global__ void __launch_bounds__(256) decode_csr_kernel(float* __restrict__ out) {
    int w = (blockIdx.x * blockDim.x + threadIdx.x) >> 5;
    int lane = threadIdx.x & 31;
    if (w >= N_NODES) return;
    int start = g_off[w];
    int cnt   = g_cnt[w];
    if (cnt == 0) return;
    int half = lane >> 4;
    int hl   = lane & 15;

    float4 zc = *(const float4*)&g_z[(size_t)w * D_O + hl * 4];

    for (int b = 0; b < cnt; b += 2) {
        int idx = b + half;
        float s = 0.0f;
        int eid = 0;
        bool ok = (idx < cnt);
        if (ok) {
            int2 se = g_cse[start + idx];
            eid = se.y;
            float4 zr = *(const float4*)&g_z[(size_t)se.x * D_O + hl * 4];
            s = zc.x * zr.x + zc.y * zr.y + zc.z * zr.z + zc.w * zr.w;
        }
        s += __shfl_xor_sync(0xffffffffu, s, 1);
        s += __shfl_xor_sync(0xffffffffu, s, 2);
        s += __shfl_xor_sync(0xffffffffu, s, 4);
        s += __shfl_xor_sync(0xffffffffu, s, 8);
        if (ok && hl == 0) out[eid] = s;
    }
}

// ---------------- launch ----------------
extern "C" void kernel_launch(void* const* d_in, const int* in_sizes, int n_in,
                              void* d_out, int out_size) {
    const float* x  = (const float*)d_in[0];
    const float* W1 = (const float*)d_in[1];
    const float* b1 = (const float*)d_in[2];
    const float* W2 = (const float*)d_in[3];
    const float* b2 = (const float*)d_in[4];
    const int*   ei = (const int*)d_in[5];
    const int E = in_sizes[5] / 2;

    static cudaStream_t s2 = nullptr;
    static cudaEvent_t evFork = nullptr, evDinv = nullptr, evCsr = nullptr;
    if (!s2) {
        cudaStreamCreateWithFlags(&s2, cudaStreamNonBlocking);
        cudaEventCreateWithFlags(&evFork, cudaEventDisableTiming);
        cudaEventCreateWithFlags(&evDinv, cudaEventDisableTiming);
        cudaEventCreateWithFlags(&evCsr,  cudaEventDisableTiming);
        cudaFuncSetAttribute(gemm1_mma_kernel,
                             cudaFuncAttributeMaxDynamicSharedMemorySize, 65536);
        cudaFuncSetAttribute(gemm2_mma_kernel,
                             cudaFuncAttributeMaxDynamicSharedMemorySize, 65536);
    }

    cudaEventRecord(evFork, 0);
    cudaStreamWaitEvent(s2, evFork, 0);

    // weight prep (main) + degree/scan/CSR chain (s2)
    wsplit_kernel<<<144, 256>>>(W1, W2);
    cnt_init_kernel<<<NB1, 256, 0, s2>>>();
    deg_count_kernel<<<(E + 255) / 256, 256, 0, s2>>>(ei + E, E);
    scan1_kernel<<<NB1, 256, 0, s2>>>();
    cudaEventRecord(evDinv, s2);
    scan2_kernel<<<1, 512, 0, s2>>>();

    // gemm1 overlaps the CSR tail
    cudaStreamWaitEvent(0, evDinv, 0);
    gemm1_mma_kernel<<<(N_NODES + 255) / 256, 512, 65536>>>(x);

    scan3b_kernel<<<NB1, 256, 0, s2>>>();
    csr_fill_kernel<<<(E + 255) / 256, 256, 0, s2>>>(ei, E);
    cudaEventRecord(evCsr, s2);

    cudaStreamWaitEvent(0, evCsr, 0);
    agg1_kernel<<<(N_NODES * 32 + 255) / 256, 256>>>();
    gemm2_mma_kernel<<<(N_NODES + 255) / 256, 512, 65536>>>(b1);
    agg2_kernel<<<(N_NODES * 32 + 255) / 256, 256>>>(b2);
    decode_csr_kernel<<<(N_NODES * 32 + 255) / 256, 256>>>((float*)d_out);
}

// round 16
// speedup vs baseline: 1.0125x; 1.0125x over previous
#include <cuda_runtime.h>
#include <cuda_bf16.h>
#include <cstdint>

#define N_NODES 100000
#define D_IN    500
#define D_H     128
#define D_O     64
#define E_MAX   3200000
#define NB1     ((N_NODES + 255) / 256)

// ---------------- scratch ----------------
__device__ int   g_cnt [N_NODES];
__device__ float g_dinv[N_NODES];
__device__ int   g_off [N_NODES];
__device__ int   g_cur [N_NODES];
__device__ int   g_part[512];
__device__ int2  g_cse [E_MAX];   // (src, eid) per in-edge, grouped by dst
// W^T bf16 hi/lo pre-packed in mma.m16n8k16 B-fragment order
__device__ __align__(16) uint32_t g_bhi[32 * 1024];   // W1
__device__ __align__(16) uint32_t g_blo[32 * 1024];
__device__ __align__(16) uint32_t g_b2hi[8 * 512];    // W2
__device__ __align__(16) uint32_t g_b2lo[8 * 512];
__device__ float g_hs  [(size_t)N_NODES * D_H];
__device__ float g_acc1[(size_t)N_NODES * D_H];
__device__ float g_hs2 [(size_t)N_NODES * D_O];
__device__ float g_z   [(size_t)N_NODES * D_O];

__device__ __forceinline__ uint32_t smem_u32(const void* p) {
    uint32_t a;
    asm("{ .reg .u64 t; cvta.to.shared.u64 t, %1; cvt.u32.u64 %0, t; }"
        : "=r"(a) : "l"(p));
    return a;
}

// ---------------- degree / CSR ----------------
__global__ void cnt_init_kernel() {
    int i = blockIdx.x * blockDim.x + threadIdx.x;
    if (i < N_NODES) g_cnt[i] = 0;
}
__global__ void deg_count_kernel(const int* __restrict__ col, int E) {
    int e = blockIdx.x * blockDim.x + threadIdx.x;
    if (e < E) atomicAdd(&g_cnt[col[e]], 1);
}
__global__ void scan1_kernel() {   // + dinv fused
    __shared__ int s[256];
    int tid = threadIdx.x;
    int i = blockIdx.x * 256 + tid;
    int v = (i < N_NODES) ? g_cnt[i] : 0;
    if (i < N_NODES) g_dinv[i] = rsqrtf((float)(v + 1));
    s[tid] = v;
    __syncthreads();
    #pragma unroll
    for (int d = 1; d < 256; d <<= 1) {
        int t = (tid >= d) ? s[tid - d] : 0;
        __syncthreads();
        s[tid] += t;
        __syncthreads();
    }
    if (i < N_NODES) g_off[i] = s[tid] - v;
    if (tid == 255) g_part[blockIdx.x] = s[255];
}
__global__ void scan2_kernel() {
    __shared__ int s[512];
    int tid = threadIdx.x;
    int v = (tid < NB1) ? g_part[tid] : 0;
    s[tid] = v;
    __syncthreads();
    #pragma unroll
    for (int d = 1; d < 512; d <<= 1) {
        int t = (tid >= d) ? s[tid - d] : 0;
        __syncthreads();
        s[tid] += t;
        __syncthreads();
    }
    if (tid < NB1) g_part[tid] = s[tid] - v;
}
__global__ void scan3b_kernel() {
    int i = blockIdx.x * blockDim.x + threadIdx.x;
    if (i < N_NODES) {
        g_off[i] += g_part[i >> 8];
        g_cur[i] = 0;
    }
}
__global__ void csr_fill_kernel(const int* __restrict__ ei, int E) {
    int e = blockIdx.x * blockDim.x + threadIdx.x;
    if (e >= E) return;
    int r = ei[e];
    int c = ei[E + e];
    int pos = g_off[c] + atomicAdd(&g_cur[c], 1);
    g_cse[pos] = make_int2(r, e);
}

// ---------------- fused W1+W2 split into mma B fragments -------------------
__global__ void wsplit_kernel(const float* __restrict__ W1,
                              const float* __restrict__ W2) {
    int i = blockIdx.x * blockDim.x + threadIdx.x;
    if (i < 32768) {
        int reg   = i & 1;
        int lane  = (i >> 1) & 31;
        int ntile = (i >> 6) & 15;
        int kstep = i >> 10;
        int n = ntile * 8 + (lane >> 2);
        int k = kstep * 16 + reg * 8 + (lane & 3) * 2;
        float w0 = (k     < D_IN) ? W1[(size_t)k * D_H + n]       : 0.0f;
        float w1 = (k + 1 < D_IN) ? W1[(size_t)(k + 1) * D_H + n] : 0.0f;
        __nv_bfloat16 h0 = __float2bfloat16(w0);
        __nv_bfloat16 h1 = __float2bfloat16(w1);
        __nv_bfloat16 l0 = __float2bfloat16(w0 - __bfloat162float(h0));
        __nv_bfloat16 l1 = __float2bfloat16(w1 - __bfloat162float(h1));
        __nv_bfloat162 hp = {h0, h1}, lp = {l0, l1};
        int idx = kstep * 1024 + (ntile >> 1) * 128 + lane * 4 + (ntile & 1) * 2 + reg;
        g_bhi[idx] = *(uint32_t*)&hp;
        g_blo[idx] = *(uint32_t*)&lp;
    } else if (i < 32768 + 4096) {
        int j = i - 32768;
        int reg   = j & 1;
        int lane  = (j >> 1) & 31;
        int ntile = (j >> 6) & 7;
        int kstep = j >> 9;
        int n = ntile * 8 + (lane >> 2);
        int k = kstep * 16 + reg * 8 + (lane & 3) * 2;
        float w0 = W2[(size_t)k * D_O + n];
        float w1 = W2[(size_t)(k + 1) * D_O + n];
        __nv_bfloat16 h0 = __float2bfloat16(w0);
        __nv_bfloat16 h1 = __float2bfloat16(w1);
        __nv_bfloat16 l0 = __float2bfloat16(w0 - __bfloat162float(h0));
        __nv_bfloat16 l1 = __float2bfloat16(w1 - __bfloat162float(h1));
        __nv_bfloat162 hp = {h0, h1}, lp = {l0, l1};
        int idx = kstep * 512 + (ntile >> 1) * 128 + lane * 4 + (ntile & 1) * 2 + reg;
        g_b2hi[idx] = *(uint32_t*)&hp;
        g_b2lo[idx] = *(uint32_t*)&lp;
    }
}

// ---------------- GEMM1: BM=256, 16 warps, 512 threads ---------------------
__global__ void __launch_bounds__(512) gemm1_mma_kernel(const float* __restrict__ X) {
    extern __shared__ __align__(16) uint8_t sm[];
    uint8_t* Ahi = sm;                // 256 rows x 128B = 32KB
    uint8_t* Alo = sm + 32768;        // 32KB

    const int tid  = threadIdx.x;
    const int wid  = tid >> 5;
    const int lane = tid & 31;
    const int m0   = blockIdx.x * 256;
    const int warp_m = (wid >> 1) * 32;
    const int warp_n = (wid & 1) * 64;

    const uint32_t ahi_base = smem_u32(Ahi);
    const uint32_t alo_base = smem_u32(Alo);

    const int arow  = tid >> 1;
    const int ahalf = tid & 1;
    const int gm    = m0 + arow;
    const float* xrow = X + (size_t)gm * D_IN;
    const bool rok = (gm < N_NODES);

    float acc[2][8][4];
    #pragma unroll
    for (int mt = 0; mt < 2; mt++)
        #pragma unroll
        for (int nt = 0; nt < 8; nt++)
            #pragma unroll
            for (int r = 0; r < 4; r++) acc[mt][nt][r] = 0.0f;

    for (int chunk = 0; chunk < 8; chunk++) {
        if (chunk > 0) __syncthreads();
        #pragma unroll
        for (int q = 0; q < 8; q++) {
            int kl = ahalf * 32 + q * 4;
            int kg = chunk * 64 + kl;
            float4 v = make_float4(0.f, 0.f, 0.f, 0.f);
            if (rok && kg < D_IN) v = *(const float4*)(xrow + kg);
            __nv_bfloat16 h0 = __float2bfloat16(v.x);
            __nv_bfloat16 h1 = __float2bfloat16(v.y);
            __nv_bfloat16 h2 = __float2bfloat16(v.z);
            __nv_bfloat16 h3 = __float2bfloat16(v.w);
            __nv_bfloat16 l0 = __float2bfloat16(v.x - __bfloat162float(h0));
            __nv_bfloat16 l1 = __float2bfloat16(v.y - __bfloat162float(h1));
            __nv_bfloat16 l2 = __float2bfloat16(v.z - __bfloat162float(h2));
            __nv_bfloat16 l3 = __float2bfloat16(v.w - __bfloat162float(h3));
            int ch  = kl >> 3;
            int sub = (kl & 7) ? 8 : 0;
            uint32_t off = arow * 128 + ((ch ^ (arow & 7)) << 4) + sub;
            __nv_bfloat162 hp0 = {h0, h1}, hp1 = {h2, h3};
            __nv_bfloat162 lp0 = {l0, l1}, lp1 = {l2, l3};
            uint2 hv = { *(uint32_t*)&hp0, *(uint32_t*)&hp1 };
            uint2 lv = { *(uint32_t*)&lp0, *(uint32_t*)&lp1 };
            *(uint2*)(Ahi + off) = hv;
            *(uint2*)(Alo + off) = lv;
        }
        __syncthreads();

        #pragma unroll
        for (int kstep = 0; kstep < 4; kstep++) {
            int kg = chunk * 4 + kstep;
            uint32_t ah[2][4], al[2][4];
            #pragma unroll
            for (int mt = 0; mt < 2; mt++) {
                int mrow = warp_m + mt * 16 + (lane & 7) + ((lane & 8) ? 8 : 0);
                int ch   = kstep * 2 + (lane >> 4);
                uint32_t off = mrow * 128 + ((ch ^ (mrow & 7)) << 4);
                asm volatile("ldmatrix.sync.aligned.m8n8.x4.shared.b16 {%0,%1,%2,%3}, [%4];"
                             : "=r"(ah[mt][0]), "=r"(ah[mt][1]), "=r"(ah[mt][2]), "=r"(ah[mt][3])
                             : "r"(ahi_base + off));
                asm volatile("ldmatrix.sync.aligned.m8n8.x4.shared.b16 {%0,%1,%2,%3}, [%4];"
                             : "=r"(al[mt][0]), "=r"(al[mt][1]), "=r"(al[mt][2]), "=r"(al[mt][3])
                             : "r"(alo_base + off));
            }
            uint4 bh[4], bl[4];
            #pragma unroll
            for (int p = 0; p < 4; p++) {
                int npair = (warp_n >> 4) + p;
                int idx = kg * 1024 + npair * 128 + lane * 4;
                bh[p] = *(const uint4*)(g_bhi + idx);
                bl[p] = *(const uint4*)(g_blo + idx);
            }
            #pragma unroll
            for (int mt = 0; mt < 2; mt++) {
                #pragma unroll
                for (int nt = 0; nt < 8; nt++) {
                    int p = nt >> 1;
                    uint32_t bh0 = (nt & 1) ? bh[p].z : bh[p].x;
                    uint32_t bh1 = (nt & 1) ? bh[p].w : bh[p].y;
                    uint32_t bl0 = (nt & 1) ? bl[p].z : bl[p].x;
                    uint32_t bl1 = (nt & 1) ? bl[p].w : bl[p].y;
                    float* c = acc[mt][nt];
                    asm volatile("mma.sync.aligned.m16n8k16.row.col.f32.bf16.bf16.f32 "
                        "{%0,%1,%2,%3}, {%4,%5,%6,%7}, {%8,%9}, {%0,%1,%2,%3};"
                        : "+f"(c[0]), "+f"(c[1]), "+f"(c[2]), "+f"(c[3])
                        : "r"(ah[mt][0]), "r"(ah[mt][1]), "r"(ah[mt][2]), "r"(ah[mt][3]),
                          "r"(bh0), "r"(bh1));
                    asm volatile("mma.sync.aligned.m16n8k16.row.col.f32.bf16.bf16.f32 "
                        "{%0,%1,%2,%3}, {%4,%5,%6,%7}, {%8,%9}, {%0,%1,%2,%3};"
                        : "+f"(c[0]), "+f"(c[1]), "+f"(c[2]), "+f"(c[3])
                        : "r"(ah[mt][0]), "r"(ah[mt][1]), "r"(ah[mt][2]), "r"(ah[mt][3]),
                          "r"(bl0), "r"(bl1));
                    asm volatile("mma.sync.aligned.m16n8k16.row.col.f32.bf16.bf16.f32 "
                        "{%0,%1,%2,%3}, {%4,%5,%6,%7}, {%8,%9}, {%0,%1,%2,%3};"
                        : "+f"(c[0]), "+f"(c[1]), "+f"(c[2]), "+f"(c[3])
                        : "r"(al[mt][0]), "r"(al[mt][1]), "r"(al[mt][2]), "r"(al[mt][3]),
                          "r"(bh0), "r"(bh1));
                }
            }
        }
    }

    #pragma unroll
    for (int mt = 0; mt < 2; mt++) {
        int r0 = m0 + warp_m + mt * 16 + (lane >> 2);
        int r1 = r0 + 8;
        float d0 = (r0 < N_NODES) ? g_dinv[r0] : 0.0f;
        float d1 = (r1 < N_NODES) ? g_dinv[r1] : 0.0f;
        #pragma unroll
        for (int nt = 0; nt < 8; nt++) {
            int cc = warp_n + nt * 8 + (lane & 3) * 2;
            if (r0 < N_NODES) {
                float2 o = make_float2(acc[mt][nt][0] * d0, acc[mt][nt][1] * d0);
                *(float2*)&g_hs[(size_t)r0 * D_H + cc] = o;
            }
            if (r1 < N_NODES) {
                float2 o = make_float2(acc[mt][nt][2] * d1, acc[mt][nt][3] * d1);
                *(float2*)&g_hs[(size_t)r1 * D_H + cc] = o;
            }
        }
    }
}

// ---------------- agg1: CSR gather, warp per node, float4 lanes ------------
__global__ void __launch_bounds__(256) agg1_kernel() {
    int w = (blockIdx.x * blockDim.x + threadIdx.x) >> 5;
    int lane = threadIdx.x & 31;
    if (w >= N_NODES) return;
    int start = g_off[w];
    int cnt   = g_cnt[w];
    const float* base = &g_hs[(size_t)lane * 4];
    float4 acc = *(const float4*)&g_hs[(size_t)w * D_H + lane * 4];

    for (int b = 0; b < cnt; b += 32) {
        int n = min(32, cnt - b);
        int src = (lane < n) ? g_cse[start + b + lane].x : 0;
        int j = 0;
        for (; j + 4 <= n; j += 4) {
            int s0 = __shfl_sync(0xffffffffu, src, j);
            int s1 = __shfl_sync(0xffffffffu, src, j + 1);
            int s2 = __shfl_sync(0xffffffffu, src, j + 2);
            int s3 = __shfl_sync(0xffffffffu, src, j + 3);
            float4 v0 = *(const float4*)(base + (size_t)s0 * D_H);
            float4 v1 = *(const float4*)(base + (size_t)s1 * D_H);
            float4 v2 = *(const float4*)(base + (size_t)s2 * D_H);
            float4 v3 = *(const float4*)(base + (size_t)s3 * D_H);
            acc.x += (v0.x + v1.x) + (v2.x + v3.x);
            acc.y += (v0.y + v1.y) + (v2.y + v3.y);
            acc.z += (v0.z + v1.z) + (v2.z + v3.z);
            acc.w += (v0.w + v1.w) + (v2.w + v3.w);
        }
        for (; j < n; j++) {
            int s = __shfl_sync(0xffffffffu, src, j);
            float4 v = *(const float4*)(base + (size_t)s * D_H);
            acc.x += v.x; acc.y += v.y; acc.z += v.z; acc.w += v.w;
        }
    }
    *(float4*)&g_acc1[(size_t)w * D_H + lane * 4] = acc;
}

// ---------------- GEMM2 (mma.sync bf16 hi/lo, 128 rows, 256 threads) -------
__global__ void __launch_bounds__(256) gemm2_mma_kernel(const float* __restrict__ b1) {
    __shared__ __align__(16) uint8_t Ahi[128 * 128];
    __shared__ __align__(16) uint8_t Alo[128 * 128];

    const int tid  = threadIdx.x;
    const int wid  = tid >> 5;
    const int lane = tid & 31;
    const int m0   = blockIdx.x * 128;
    const int warp_m = (wid >> 1) * 32;
    const int warp_n = (wid & 1) * 32;

    const uint32_t ahi_base = smem_u32(Ahi);
    const uint32_t alo_base = smem_u32(Alo);

    const int arow  = tid >> 1;
    const int ahalf = tid & 1;
    const int gm    = m0 + arow;
    const bool rok = (gm < N_NODES);
    const float dA = rok ? g_dinv[gm] : 0.0f;
    const float* arowp = g_acc1 + (size_t)gm * D_H;

    float acc[2][4][4];
    #pragma unroll
    for (int mt = 0; mt < 2; mt++)
        #pragma unroll
        for (int nt = 0; nt < 4; nt++)
            #pragma unroll
            for (int r = 0; r < 4; r++) acc[mt][nt][r] = 0.0f;

    for (int chunk = 0; chunk < 2; chunk++) {
        if (chunk > 0) __syncthreads();
        #pragma unroll
        for (int q = 0; q < 8; q++) {
            int kl = ahalf * 32 + q * 4;
            int kg = chunk * 64 + kl;
            float4 v = make_float4(0.f, 0.f, 0.f, 0.f);
            if (rok) {
                float4 a = *(const float4*)(arowp + kg);
                float4 bb = *(const float4*)(b1 + kg);
                v.x = fmaxf(fmaf(a.x, dA, bb.x), 0.0f);
                v.y = fmaxf(fmaf(a.y, dA, bb.y), 0.0f);
                v.z = fmaxf(fmaf(a.z, dA, bb.z), 0.0f);
                v.w = fmaxf(fmaf(a.w, dA, bb.w), 0.0f);
            }
            __nv_bfloat16 h0 = __float2bfloat16(v.x);
            __nv_bfloat16 h1 = __float2bfloat16(v.y);
            __nv_bfloat16 h2 = __float2bfloat16(v.z);
            __nv_bfloat16 h3 = __float2bfloat16(v.w);
            __nv_bfloat16 l0 = __float2bfloat16(v.x - __bfloat162float(h0));
            __nv_bfloat16 l1 = __float2bfloat16(v.y - __bfloat162float(h1));
            __nv_bfloat16 l2 = __float2bfloat16(v.z - __bfloat162float(h2));
            __nv_bfloat16 l3 = __float2bfloat16(v.w - __bfloat162float(h3));
            int ch  = kl >> 3;
            int sub = (kl & 7) ? 8 : 0;
            uint32_t off = arow * 128 + ((ch ^ (arow & 7)) << 4) + sub;
            __nv_bfloat162 hp0 = {h0, h1}, hp1 = {h2, h3};
            __nv_bfloat162 lp0 = {l0, l1}, lp1 = {l2, l3};
            uint2 hv = { *(uint32_t*)&hp0, *(uint32_t*)&hp1 };
            uint2 lv = { *(uint32_t*)&lp0, *(uint32_t*)&lp1 };
            *(uint2*)(Ahi + off) = hv;
            *(uint2*)(Alo + off) = lv;
        }
        __syncthreads();

        #pragma unroll
        for (int kstep = 0; kstep < 4; kstep++) {
            int kg = chunk * 4 + kstep;
            uint32_t ah[2][4], al[2][4];
            #pragma unroll
            for (int mt = 0; mt < 2; mt++) {
                int mrow = warp_m + mt * 16 + (lane & 15);
                int ch   = kstep * 2 + (lane >> 4);
                uint32_t off = mrow * 128 + ((ch ^ (mrow & 7)) << 4);
                asm volatile("ldmatrix.sync.aligned.m8n8.x4.shared.b16 {%0,%1,%2,%3}, [%4];"
                             : "=r"(ah[mt][0]), "=r"(ah[mt][1]), "=r"(ah[mt][2]), "=r"(ah[mt][3])
                             : "r"(ahi_base + off));
                asm volatile("ldmatrix.sync.aligned.m8n8.x4.shared.b16 {%0,%1,%2,%3}, [%4];"
                             : "=r"(al[mt][0]), "=r"(al[mt][1]), "=r"(al[mt][2]), "=r"(al[mt][3])
                             : "r"(alo_base + off));
            }
            uint4 bh[2], bl[2];
            #pragma unroll
            for (int p = 0; p < 2; p++) {
                int npair = (warp_n >> 4) + p;
                int idx = kg * 512 + npair * 128 + lane * 4;
                bh[p] = *(const uint4*)(g_b2hi + idx);
                bl[p] = *(const uint4*)(g_b2lo + idx);
            }
            #pragma unroll
            for (int mt = 0; mt < 2; mt++) {
                #pragma unroll
                for (int nt = 0; nt < 4; nt++) {
                    int p = nt >> 1;
                    uint32_t bh0 = (nt & 1) ? bh[p].z : bh[p].x;
                    uint32_t bh1 = (nt & 1) ? bh[p].w : bh[p].y;
                    uint32_t bl0 = (nt & 1) ? bl[p].z : bl[p].x;
                    uint32_t bl1 = (nt & 1) ? bl[p].w : bl[p].y;
                    float* c = acc[mt][nt];
                    asm volatile("mma.sync.aligned.m16n8k16.row.col.f32.bf16.bf16.f32 "
                        "{%0,%1,%2,%3}, {%4,%5,%6,%7}, {%8,%9}, {%0,%1,%2,%3};"
                        : "+f"(c[0]), "+f"(c[1]), "+f"(c[2]), "+f"(c[3])
                        : "r"(ah[mt][0]), "r"(ah[mt][1]), "r"(ah[mt][2]), "r"(ah[mt][3]),
                          "r"(bh0), "r"(bh1));
                    asm volatile("mma.sync.aligned.m16n8k16.row.col.f32.bf16.bf16.f32 "
                        "{%0,%1,%2,%3}, {%4,%5,%6,%7}, {%8,%9}, {%0,%1,%2,%3};"
                        : "+f"(c[0]), "+f"(c[1]), "+f"(c[2]), "+f"(c[3])
                        : "r"(ah[mt][0]), "r"(ah[mt][1]), "r"(ah[mt][2]), "r"(ah[mt][3]),
                          "r"(bl0), "r"(bl1));
                    asm volatile("mma.sync.aligned.m16n8k16.row.col.f32.bf16.bf16.f32 "
                        "{%0,%1,%2,%3}, {%4,%5,%6,%7}, {%8,%9}, {%0,%1,%2,%3};"
                        : "+f"(c[0]), "+f"(c[1]), "+f"(c[2]), "+f"(c[3])
                        : "r"(al[mt][0]), "r"(al[mt][1]), "r"(al[mt][2]), "r"(al[mt][3]),
                          "r"(bh0), "r"(bh1));
                }
            }
        }
    }

    #pragma unroll
    for (int mt = 0; mt < 2; mt++) {
        int r0 = m0 + warp_m + mt * 16 + (lane >> 2);
        int r1 = r0 + 8;
        float d0 = (r0 < N_NODES) ? g_dinv[r0] : 0.0f;
        float d1 = (r1 < N_NODES) ? g_dinv[r1] : 0.0f;
        #pragma unroll
        for (int nt = 0; nt < 4; nt++) {
            int cc = warp_n + nt * 8 + (lane & 3) * 2;
            if (r0 < N_NODES) {
                float2 o = make_float2(acc[mt][nt][0] * d0, acc[mt][nt][1] * d0);
                *(float2*)&g_hs2[(size_t)r0 * D_O + cc] = o;
            }
            if (r1 < N_NODES) {
                float2 o = make_float2(acc[mt][nt][2] * d1, acc[mt][nt][3] * d1);
                *(float2*)&g_hs2[(size_t)r1 * D_O + cc] = o;
            }
        }
    }
}

// ---------------- agg2: CSR gather, warp per node, float2 lanes ------------
__global__ void __launch_bounds__(256) agg2_kernel(const float* __restrict__ b2) {
    int w = (blockIdx.x * blockDim.x + threadIdx.x) >> 5;
    int lane = threadIdx.x & 31;
    if (w >= N_NODES) return;
    int start = g_off[w];
    int cnt   = g_cnt[w];
    const float* base = &g_hs2[(size_t)lane * 2];
    float2 acc = *(const float2*)&g_hs2[(size_t)w * D_O + lane * 2];

    for (int b = 0; b < cnt; b += 32) {
        int n = min(32, cnt - b);
        int src = (lane < n) ? g_cse[start + b + lane].x : 0;
        int j = 0;
        for (; j + 4 <= n; j += 4) {
            int s0 = __shfl_sync(0xffffffffu, src, j);
            int s1 = __shfl_sync(0xffffffffu, src, j + 1);
            int s2 = __shfl_sync(0xffffffffu, src, j + 2);
            int s3 = __shfl_sync(0xffffffffu, src, j + 3);
            float2 v0 = *(const float2*)(base + (size_t)s0 * D_O);
            float2 v1 = *(const float2*)(base + (size_t)s1 * D_O);
            float2 v2 = *(const float2*)(base + (size_t)s2 * D_O);
            float2 v3 = *(const float2*)(base + (size_t)s3 * D_O);
            acc.x += (v0.x + v1.x) + (v2.x + v3.x);
            acc.y += (v0.y + v1.y) + (v2.y + v3.y);
        }
        for (; j < n; j++) {
            int s = __shfl_sync(0xffffffffu, src, j);
            float2 v = *(const float2*)(base + (size_t)s * D_O);
            acc.x += v.x; acc.y += v.y;
        }
    }
    float d = g_dinv[w];
    float2 z = make_float2(fmaf(acc.x, d, b2[lane * 2]),
                           fmaf(acc.y, d, b2[lane * 2 + 1]));
    *(float2*)&g_z[(size_t)w * D_O + lane * 2] = z;
}

// ---------------- decode (CSR order): warp per dst node -------------------
__global__ void __launch_bounds__(256) decode_csr_kernel(float* __restrict__ out) {
    int w = (blockIdx.x * blockDim.x + threadIdx.x) >> 5;
    int lane = threadIdx.x & 31;
    if (w >= N_NODES) return;
    int start = g_off[w];
    int cnt   = g_cnt[w];
    if (cnt == 0) return;
    int half = lane >> 4;
    int hl   = lane & 15;

    float4 zc = *(const float4*)&g_z[(size_t)w * D_O + hl * 4];

    for (int b = 0; b < cnt; b += 2) {
        int idx = b + half;
        float s = 0.0f;
        int eid = 0;
        bool ok = (idx < cnt);
        if (ok) {
            int2 se = g_cse[start + idx];
            eid = se.y;
            float4 zr = *(const float4*)&g_z[(size_t)se.x * D_O + hl * 4];
            s = zc.x * zr.x + zc.y * zr.y + zc.z * zr.z + zc.w * zr.w;
        }
        s += __shfl_xor_sync(0xffffffffu, s, 1);
        s += __shfl_xor_sync(0xffffffffu, s, 2);
        s += __shfl_xor_sync(0xffffffffu, s, 4);
        s += __shfl_xor_sync(0xffffffffu, s, 8);
        if (ok && hl == 0) out[eid] = s;
    }
}

// ---------------- launch ----------------
extern "C" void kernel_launch(void* const* d_in, const int* in_sizes, int n_in,
                              void* d_out, int out_size) {
    const float* x  = (const float*)d_in[0];
    const float* W1 = (const float*)d_in[1];
    const float* b1 = (const float*)d_in[2];
    const float* W2 = (const float*)d_in[3];
    const float* b2 = (const float*)d_in[4];
    const int*   ei = (const int*)d_in[5];
    const int E = in_sizes[5] / 2;

    static cudaStream_t s2 = nullptr;
    static cudaEvent_t evFork = nullptr, evDinv = nullptr, evCsr = nullptr;
    if (!s2) {
        cudaStreamCreateWithFlags(&s2, cudaStreamNonBlocking);
        cudaEventCreateWithFlags(&evFork, cudaEventDisableTiming);
        cudaEventCreateWithFlags(&evDinv, cudaEventDisableTiming);
        cudaEventCreateWithFlags(&evCsr,  cudaEventDisableTiming);
        cudaFuncSetAttribute(gemm1_mma_kernel,
                             cudaFuncAttributeMaxDynamicSharedMemorySize, 65536);
    }

    cudaEventRecord(evFork, 0);
    cudaStreamWaitEvent(s2, evFork, 0);

    // weight prep (main) + degree/scan/CSR chain (s2)
    wsplit_kernel<<<144, 256>>>(W1, W2);
    cnt_init_kernel<<<NB1, 256, 0, s2>>>();
    deg_count_kernel<<<(E + 255) / 256, 256, 0, s2>>>(ei + E, E);
    scan1_kernel<<<NB1, 256, 0, s2>>>();
    cudaEventRecord(evDinv, s2);
    scan2_kernel<<<1, 512, 0, s2>>>();

    // gemm1 overlaps the CSR tail (BM=256 → 391 CTAs, 512 threads, 64KB smem)
    cudaStreamWaitEvent(0, evDinv, 0);
    gemm1_mma_kernel<<<(N_NODES + 255) / 256, 512, 65536>>>(x);

    scan3b_kernel<<<NB1, 256, 0, s2>>>();
    csr_fill_kernel<<<(E + 255) / 256, 256, 0, s2>>>(ei, E);
    cudaEventRecord(evCsr, s2);

    cudaStreamWaitEvent(0, evCsr, 0);
    agg1_kernel<<<(N_NODES * 32 + 255) / 256, 256>>>();
    gemm2_mma_kernel<<<(N_NODES + 127) / 128, 256>>>(b1);
    agg2_kernel<<<(N_NODES * 32 + 255) / 256, 256>>>(b2);
    decode_csr_kernel<<<(N_NODES * 32 + 255) / 256, 256>>>((float*)d_out);
}

// round 17
// speedup vs baseline: 1.0748x; 1.0615x over previous
#include <cuda_runtime.h>
#include <cuda_bf16.h>
#include <cuda_fp16.h>
#include <cstdint>

#define N_NODES 100000
#define D_IN    500
#define D_H     128
#define D_O     64
#define E_MAX   3200000
#define NB1     ((N_NODES + 255) / 256)

// ---------------- scratch ----------------
__device__ int   g_cnt [N_NODES];
__device__ float g_dinv[N_NODES];
__device__ int   g_off [N_NODES];
__device__ int   g_cur [N_NODES];
__device__ int   g_part[512];
__device__ int2  g_cse [E_MAX];   // (src, eid) per in-edge, grouped by dst
// W^T bf16 hi/lo pre-packed in mma.m16n8k16 B-fragment order
__device__ __align__(16) uint32_t g_bhi[32 * 1024];   // W1
__device__ __align__(16) uint32_t g_blo[32 * 1024];
__device__ __align__(16) uint32_t g_b2hi[8 * 512];    // W2
__device__ __align__(16) uint32_t g_b2lo[8 * 512];
// hs stored as fp16 (half2 words): only consumer is agg1's L2 gather
__device__ __align__(16) uint32_t g_hs16[(size_t)N_NODES * 64];
__device__ float g_acc1[(size_t)N_NODES * D_H];
__device__ float g_hs2 [(size_t)N_NODES * D_O];
__device__ float g_z   [(size_t)N_NODES * D_O];

__device__ __forceinline__ uint32_t smem_u32(const void* p) {
    uint32_t a;
    asm("{ .reg .u64 t; cvta.to.shared.u64 t, %1; cvt.u32.u64 %0, t; }"
        : "=r"(a) : "l"(p));
    return a;
}

// ---------------- degree / CSR ----------------
__global__ void cnt_init_kernel() {
    int i = blockIdx.x * blockDim.x + threadIdx.x;
    if (i < N_NODES) g_cnt[i] = 0;
}
__global__ void deg_count_kernel(const int* __restrict__ col, int E) {
    int e = blockIdx.x * blockDim.x + threadIdx.x;
    if (e < E) atomicAdd(&g_cnt[col[e]], 1);
}
__global__ void scan1_kernel() {   // + dinv fused
    __shared__ int s[256];
    int tid = threadIdx.x;
    int i = blockIdx.x * 256 + tid;
    int v = (i < N_NODES) ? g_cnt[i] : 0;
    if (i < N_NODES) g_dinv[i] = rsqrtf((float)(v + 1));
    s[tid] = v;
    __syncthreads();
    #pragma unroll
    for (int d = 1; d < 256; d <<= 1) {
        int t = (tid >= d) ? s[tid - d] : 0;
        __syncthreads();
        s[tid] += t;
        __syncthreads();
    }
    if (i < N_NODES) g_off[i] = s[tid] - v;
    if (tid == 255) g_part[blockIdx.x] = s[255];
}
__global__ void scan2_kernel() {
    __shared__ int s[512];
    int tid = threadIdx.x;
    int v = (tid < NB1) ? g_part[tid] : 0;
    s[tid] = v;
    __syncthreads();
    #pragma unroll
    for (int d = 1; d < 512; d <<= 1) {
        int t = (tid >= d) ? s[tid - d] : 0;
        __syncthreads();
        s[tid] += t;
        __syncthreads();
    }
    if (tid < NB1) g_part[tid] = s[tid] - v;
}
__global__ void scan3b_kernel() {
    int i = blockIdx.x * blockDim.x + threadIdx.x;
    if (i < N_NODES) {
        g_off[i] += g_part[i >> 8];
        g_cur[i] = 0;
    }
}
__global__ void csr_fill_kernel(const int* __restrict__ ei, int E) {
    int e = blockIdx.x * blockDim.x + threadIdx.x;
    if (e >= E) return;
    int r = ei[e];
    int c = ei[E + e];
    int pos = g_off[c] + atomicAdd(&g_cur[c], 1);
    g_cse[pos] = make_int2(r, e);
}

// ---------------- fused W1+W2 split into mma B fragments -------------------
__global__ void wsplit_kernel(const float* __restrict__ W1,
                              const float* __restrict__ W2) {
    int i = blockIdx.x * blockDim.x + threadIdx.x;
    if (i < 32768) {
        int reg   = i & 1;
        int lane  = (i >> 1) & 31;
        int ntile = (i >> 6) & 15;
        int kstep = i >> 10;
        int n = ntile * 8 + (lane >> 2);
        int k = kstep * 16 + reg * 8 + (lane & 3) * 2;
        float w0 = (k     < D_IN) ? W1[(size_t)k * D_H + n]       : 0.0f;
        float w1 = (k + 1 < D_IN) ? W1[(size_t)(k + 1) * D_H + n] : 0.0f;
        __nv_bfloat16 h0 = __float2bfloat16(w0);
        __nv_bfloat16 h1 = __float2bfloat16(w1);
        __nv_bfloat16 l0 = __float2bfloat16(w0 - __bfloat162float(h0));
        __nv_bfloat16 l1 = __float2bfloat16(w1 - __bfloat162float(h1));
        __nv_bfloat162 hp = {h0, h1}, lp = {l0, l1};
        int idx = kstep * 1024 + (ntile >> 1) * 128 + lane * 4 + (ntile & 1) * 2 + reg;
        g_bhi[idx] = *(uint32_t*)&hp;
        g_blo[idx] = *(uint32_t*)&lp;
    } else if (i < 32768 + 4096) {
        int j = i - 32768;
        int reg   = j & 1;
        int lane  = (j >> 1) & 31;
        int ntile = (j >> 6) & 7;
        int kstep = j >> 9;
        int n = ntile * 8 + (lane >> 2);
        int k = kstep * 16 + reg * 8 + (lane & 3) * 2;
        float w0 = W2[(size_t)k * D_O + n];
        float w1 = W2[(size_t)(k + 1) * D_O + n];
        __nv_bfloat16 h0 = __float2bfloat16(w0);
        __nv_bfloat16 h1 = __float2bfloat16(w1);
        __nv_bfloat16 l0 = __float2bfloat16(w0 - __bfloat162float(h0));
        __nv_bfloat16 l1 = __float2bfloat16(w1 - __bfloat162float(h1));
        __nv_bfloat162 hp = {h0, h1}, lp = {l0, l1};
        int idx = kstep * 512 + (ntile >> 1) * 128 + lane * 4 + (ntile & 1) * 2 + reg;
        g_b2hi[idx] = *(uint32_t*)&hp;
        g_b2lo[idx] = *(uint32_t*)&lp;
    }
}

// ---------------- GEMM1: BM=256, 16 warps, 512 threads ---------------------
// Epilogue writes g_hs16 (fp16 half2) — halved store traffic.
__global__ void __launch_bounds__(512) gemm1_mma_kernel(const float* __restrict__ X) {
    extern __shared__ __align__(16) uint8_t sm[];
    uint8_t* Ahi = sm;                // 256 rows x 128B = 32KB
    uint8_t* Alo = sm + 32768;        // 32KB

    const int tid  = threadIdx.x;
    const int wid  = tid >> 5;
    const int lane = tid & 31;
    const int m0   = blockIdx.x * 256;
    const int warp_m = (wid >> 1) * 32;
    const int warp_n = (wid & 1) * 64;

    const uint32_t ahi_base = smem_u32(Ahi);
    const uint32_t alo_base = smem_u32(Alo);

    const int arow  = tid >> 1;
    const int ahalf = tid & 1;
    const int gm    = m0 + arow;
    const float* xrow = X + (size_t)gm * D_IN;
    const bool rok = (gm < N_NODES);

    float acc[2][8][4];
    #pragma unroll
    for (int mt = 0; mt < 2; mt++)
        #pragma unroll
        for (int nt = 0; nt < 8; nt++)
            #pragma unroll
            for (int r = 0; r < 4; r++) acc[mt][nt][r] = 0.0f;

    for (int chunk = 0; chunk < 8; chunk++) {
        if (chunk > 0) __syncthreads();
        #pragma unroll
        for (int q = 0; q < 8; q++) {
            int kl = ahalf * 32 + q * 4;
            int kg = chunk * 64 + kl;
            float4 v = make_float4(0.f, 0.f, 0.f, 0.f);
            if (rok && kg < D_IN) v = *(const float4*)(xrow + kg);
            __nv_bfloat16 h0 = __float2bfloat16(v.x);
            __nv_bfloat16 h1 = __float2bfloat16(v.y);
            __nv_bfloat16 h2 = __float2bfloat16(v.z);
            __nv_bfloat16 h3 = __float2bfloat16(v.w);
            __nv_bfloat16 l0 = __float2bfloat16(v.x - __bfloat162float(h0));
            __nv_bfloat16 l1 = __float2bfloat16(v.y - __bfloat162float(h1));
            __nv_bfloat16 l2 = __float2bfloat16(v.z - __bfloat162float(h2));
            __nv_bfloat16 l3 = __float2bfloat16(v.w - __bfloat162float(h3));
            int ch  = kl >> 3;
            int sub = (kl & 7) ? 8 : 0;
            uint32_t off = arow * 128 + ((ch ^ (arow & 7)) << 4) + sub;
            __nv_bfloat162 hp0 = {h0, h1}, hp1 = {h2, h3};
            __nv_bfloat162 lp0 = {l0, l1}, lp1 = {l2, l3};
            uint2 hv = { *(uint32_t*)&hp0, *(uint32_t*)&hp1 };
            uint2 lv = { *(uint32_t*)&lp0, *(uint32_t*)&lp1 };
            *(uint2*)(Ahi + off) = hv;
            *(uint2*)(Alo + off) = lv;
        }
        __syncthreads();

        #pragma unroll
        for (int kstep = 0; kstep < 4; kstep++) {
            int kg = chunk * 4 + kstep;
            uint32_t ah[2][4], al[2][4];
            #pragma unroll
            for (int mt = 0; mt < 2; mt++) {
                int mrow = warp_m + mt * 16 + (lane & 7) + ((lane & 8) ? 8 : 0);
                int ch   = kstep * 2 + (lane >> 4);
                uint32_t off = mrow * 128 + ((ch ^ (mrow & 7)) << 4);
                asm volatile("ldmatrix.sync.aligned.m8n8.x4.shared.b16 {%0,%1,%2,%3}, [%4];"
                             : "=r"(ah[mt][0]), "=r"(ah[mt][1]), "=r"(ah[mt][2]), "=r"(ah[mt][3])
                             : "r"(ahi_base + off));
                asm volatile("ldmatrix.sync.aligned.m8n8.x4.shared.b16 {%0,%1,%2,%3}, [%4];"
                             : "=r"(al[mt][0]), "=r"(al[mt][1]), "=r"(al[mt][2]), "=r"(al[mt][3])
                             : "r"(alo_base + off));
            }
            uint4 bh[4], bl[4];
            #pragma unroll
            for (int p = 0; p < 4; p++) {
                int npair = (warp_n >> 4) + p;
                int idx = kg * 1024 + npair * 128 + lane * 4;
                bh[p] = *(const uint4*)(g_bhi + idx);
                bl[p] = *(const uint4*)(g_blo + idx);
            }
            #pragma unroll
            for (int mt = 0; mt < 2; mt++) {
                #pragma unroll
                for (int nt = 0; nt < 8; nt++) {
                    int p = nt >> 1;
                    uint32_t bh0 = (nt & 1) ? bh[p].z : bh[p].x;
                    uint32_t bh1 = (nt & 1) ? bh[p].w : bh[p].y;
                    uint32_t bl0 = (nt & 1) ? bl[p].z : bl[p].x;
                    uint32_t bl1 = (nt & 1) ? bl[p].w : bl[p].y;
                    float* c = acc[mt][nt];
                    asm volatile("mma.sync.aligned.m16n8k16.row.col.f32.bf16.bf16.f32 "
                        "{%0,%1,%2,%3}, {%4,%5,%6,%7}, {%8,%9}, {%0,%1,%2,%3};"
                        : "+f"(c[0]), "+f"(c[1]), "+f"(c[2]), "+f"(c[3])
                        : "r"(ah[mt][0]), "r"(ah[mt][1]), "r"(ah[mt][2]), "r"(ah[mt][3]),
                          "r"(bh0), "r"(bh1));
                    asm volatile("mma.sync.aligned.m16n8k16.row.col.f32.bf16.bf16.f32 "
                        "{%0,%1,%2,%3}, {%4,%5,%6,%7}, {%8,%9}, {%0,%1,%2,%3};"
                        : "+f"(c[0]), "+f"(c[1]), "+f"(c[2]), "+f"(c[3])
                        : "r"(ah[mt][0]), "r"(ah[mt][1]), "r"(ah[mt][2]), "r"(ah[mt][3]),
                          "r"(bl0), "r"(bl1));
                    asm volatile("mma.sync.aligned.m16n8k16.row.col.f32.bf16.bf16.f32 "
                        "{%0,%1,%2,%3}, {%4,%5,%6,%7}, {%8,%9}, {%0,%1,%2,%3};"
                        : "+f"(c[0]), "+f"(c[1]), "+f"(c[2]), "+f"(c[3])
                        : "r"(al[mt][0]), "r"(al[mt][1]), "r"(al[mt][2]), "r"(al[mt][3]),
                          "r"(bh0), "r"(bh1));
                }
            }
        }
    }

    #pragma unroll
    for (int mt = 0; mt < 2; mt++) {
        int r0 = m0 + warp_m + mt * 16 + (lane >> 2);
        int r1 = r0 + 8;
        float d0 = (r0 < N_NODES) ? g_dinv[r0] : 0.0f;
        float d1 = (r1 < N_NODES) ? g_dinv[r1] : 0.0f;
        #pragma unroll
        for (int nt = 0; nt < 8; nt++) {
            int cc = warp_n + nt * 8 + (lane & 3) * 2;
            if (r0 < N_NODES) {
                float2 o = make_float2(acc[mt][nt][0] * d0, acc[mt][nt][1] * d0);
                __half2 hh = __float22half2_rn(o);
                g_hs16[(size_t)r0 * 64 + (cc >> 1)] = *(uint32_t*)&hh;
            }
            if (r1 < N_NODES) {
                float2 o = make_float2(acc[mt][nt][2] * d1, acc[mt][nt][3] * d1);
                __half2 hh = __float22half2_rn(o);
                g_hs16[(size_t)r1 * 64 + (cc >> 1)] = *(uint32_t*)&hh;
            }
        }
    }
}

// ---------------- agg1: CSR gather (fp16 rows), warp per node --------------
// Each lane: 4 columns = 2 half2 words = 8B. Row = 256B. fp32 accumulate.
__global__ void __launch_bounds__(256) agg1_kernel() {
    int w = (blockIdx.x * blockDim.x + threadIdx.x) >> 5;
    int lane = threadIdx.x & 31;
    if (w >= N_NODES) return;
    int start = g_off[w];
    int cnt   = g_cnt[w];
    const uint32_t* base = g_hs16 + lane * 2;

    float4 acc;
    {
        uint2 sv = *(const uint2*)(g_hs16 + (size_t)w * 64 + lane * 2);
        float2 a = __half22float2(*(__half2*)&sv.x);
        float2 b = __half22float2(*(__half2*)&sv.y);
        acc = make_float4(a.x, a.y, b.x, b.y);
    }

    for (int b = 0; b < cnt; b += 32) {
        int n = min(32, cnt - b);
        int src = (lane < n) ? g_cse[start + b + lane].x : 0;
        int j = 0;
        for (; j + 4 <= n; j += 4) {
            int s0 = __shfl_sync(0xffffffffu, src, j);
            int s1 = __shfl_sync(0xffffffffu, src, j + 1);
            int s2 = __shfl_sync(0xffffffffu, src, j + 2);
            int s3 = __shfl_sync(0xffffffffu, src, j + 3);
            uint2 v0 = *(const uint2*)(base + (size_t)s0 * 64);
            uint2 v1 = *(const uint2*)(base + (size_t)s1 * 64);
            uint2 v2 = *(const uint2*)(base + (size_t)s2 * 64);
            uint2 v3 = *(const uint2*)(base + (size_t)s3 * 64);
            float2 a0 = __half22float2(*(__half2*)&v0.x), b0 = __half22float2(*(__half2*)&v0.y);
            float2 a1 = __half22float2(*(__half2*)&v1.x), b1 = __half22float2(*(__half2*)&v1.y);
            float2 a2 = __half22float2(*(__half2*)&v2.x), b2 = __half22float2(*(__half2*)&v2.y);
            float2 a3 = __half22float2(*(__half2*)&v3.x), b3 = __half22float2(*(__half2*)&v3.y);
            acc.x += (a0.x + a1.x) + (a2.x + a3.x);
            acc.y += (a0.y + a1.y) + (a2.y + a3.y);
            acc.z += (b0.x + b1.x) + (b2.x + b3.x);
            acc.w += (b0.y + b1.y) + (b2.y + b3.y);
        }
        for (; j < n; j++) {
            int s = __shfl_sync(0xffffffffu, src, j);
            uint2 v = *(const uint2*)(base + (size_t)s * 64);
            float2 a = __half22float2(*(__half2*)&v.x);
            float2 b2v = __half22float2(*(__half2*)&v.y);
            acc.x += a.x; acc.y += a.y; acc.z += b2v.x; acc.w += b2v.y;
        }
    }
    *(float4*)&g_acc1[(size_t)w * D_H + lane * 4] = acc;
}

// ---------------- GEMM2 (mma.sync bf16 hi/lo, 128 rows, 256 threads) -------
__global__ void __launch_bounds__(256) gemm2_mma_kernel(const float* __restrict__ b1) {
    __shared__ __align__(16) uint8_t Ahi[128 * 128];
    __shared__ __align__(16) uint8_t Alo[128 * 128];

    const int tid  = threadIdx.x;
    const int wid  = tid >> 5;
    const int lane = tid & 31;
    const int m0   = blockIdx.x * 128;
    const int warp_m = (wid >> 1) * 32;
    const int warp_n = (wid & 1) * 32;

    const uint32_t ahi_base = smem_u32(Ahi);
    const uint32_t alo_base = smem_u32(Alo);

    const int arow  = tid >> 1;
    const int ahalf = tid & 1;
    const int gm    = m0 + arow;
    const bool rok = (gm < N_NODES);
    const float dA = rok ? g_dinv[gm] : 0.0f;
    const float* arowp = g_acc1 + (size_t)gm * D_H;

    float acc[2][4][4];
    #pragma unroll
    for (int mt = 0; mt < 2; mt++)
        #pragma unroll
        for (int nt = 0; nt < 4; nt++)
            #pragma unroll
            for (int r = 0; r < 4; r++) acc[mt][nt][r] = 0.0f;

    for (int chunk = 0; chunk < 2; chunk++) {
        if (chunk > 0) __syncthreads();
        #pragma unroll
        for (int q = 0; q < 8; q++) {
            int kl = ahalf * 32 + q * 4;
            int kg = chunk * 64 + kl;
            float4 v = make_float4(0.f, 0.f, 0.f, 0.f);
            if (rok) {
                float4 a = *(const float4*)(arowp + kg);
                float4 bb = *(const float4*)(b1 + kg);
                v.x = fmaxf(fmaf(a.x, dA, bb.x), 0.0f);
                v.y = fmaxf(fmaf(a.y, dA, bb.y), 0.0f);
                v.z = fmaxf(fmaf(a.z, dA, bb.z), 0.0f);
                v.w = fmaxf(fmaf(a.w, dA, bb.w), 0.0f);
            }
            __nv_bfloat16 h0 = __float2bfloat16(v.x);
            __nv_bfloat16 h1 = __float2bfloat16(v.y);
            __nv_bfloat16 h2 = __float2bfloat16(v.z);
            __nv_bfloat16 h3 = __float2bfloat16(v.w);
            __nv_bfloat16 l0 = __float2bfloat16(v.x - __bfloat162float(h0));
            __nv_bfloat16 l1 = __float2bfloat16(v.y - __bfloat162float(h1));
            __nv_bfloat16 l2 = __float2bfloat16(v.z - __bfloat162float(h2));
            __nv_bfloat16 l3 = __float2bfloat16(v.w - __bfloat162float(h3));
            int ch  = kl >> 3;
            int sub = (kl & 7) ? 8 : 0;
            uint32_t off = arow * 128 + ((ch ^ (arow & 7)) << 4) + sub;
            __nv_bfloat162 hp0 = {h0, h1}, hp1 = {h2, h3};
            __nv_bfloat162 lp0 = {l0, l1}, lp1 = {l2, l3};
            uint2 hv = { *(uint32_t*)&hp0, *(uint32_t*)&hp1 };
            uint2 lv = { *(uint32_t*)&lp0, *(uint32_t*)&lp1 };
            *(uint2*)(Ahi + off) = hv;
            *(uint2*)(Alo + off) = lv;
        }
        __syncthreads();

        #pragma unroll
        for (int kstep = 0; kstep < 4; kstep++) {
            int kg = chunk * 4 + kstep;
            uint32_t ah[2][4], al[2][4];
            #pragma unroll
            for (int mt = 0; mt < 2; mt++) {
                int mrow = warp_m + mt * 16 + (lane & 15);
                int ch   = kstep * 2 + (lane >> 4);
                uint32_t off = mrow * 128 + ((ch ^ (mrow & 7)) << 4);
                asm volatile("ldmatrix.sync.aligned.m8n8.x4.shared.b16 {%0,%1,%2,%3}, [%4];"
                             : "=r"(ah[mt][0]), "=r"(ah[mt][1]), "=r"(ah[mt][2]), "=r"(ah[mt][3])
                             : "r"(ahi_base + off));
                asm volatile("ldmatrix.sync.aligned.m8n8.x4.shared.b16 {%0,%1,%2,%3}, [%4];"
                             : "=r"(al[mt][0]), "=r"(al[mt][1]), "=r"(al[mt][2]), "=r"(al[mt][3])
                             : "r"(alo_base + off));
            }
            uint4 bh[2], bl[2];
            #pragma unroll
            for (int p = 0; p < 2; p++) {
                int npair = (warp_n >> 4) + p;
                int idx = kg * 512 + npair * 128 + lane * 4;
                bh[p] = *(const uint4*)(g_b2hi + idx);
                bl[p] = *(const uint4*)(g_b2lo + idx);
            }
            #pragma unroll
            for (int mt = 0; mt < 2; mt++) {
                #pragma unroll
                for (int nt = 0; nt < 4; nt++) {
                    int p = nt >> 1;
                    uint32_t bh0 = (nt & 1) ? bh[p].z : bh[p].x;
                    uint32_t bh1 = (nt & 1) ? bh[p].w : bh[p].y;
                    uint32_t bl0 = (nt & 1) ? bl[p].z : bl[p].x;
                    uint32_t bl1 = (nt & 1) ? bl[p].w : bl[p].y;
                    float* c = acc[mt][nt];
                    asm volatile("mma.sync.aligned.m16n8k16.row.col.f32.bf16.bf16.f32 "
                        "{%0,%1,%2,%3}, {%4,%5,%6,%7}, {%8,%9}, {%0,%1,%2,%3};"
                        : "+f"(c[0]), "+f"(c[1]), "+f"(c[2]), "+f"(c[3])
                        : "r"(ah[mt][0]), "r"(ah[mt][1]), "r"(ah[mt][2]), "r"(ah[mt][3]),
                          "r"(bh0), "r"(bh1));
                    asm volatile("mma.sync.aligned.m16n8k16.row.col.f32.bf16.bf16.f32 "
                        "{%0,%1,%2,%3}, {%4,%5,%6,%7}, {%8,%9}, {%0,%1,%2,%3};"
                        : "+f"(c[0]), "+f"(c[1]), "+f"(c[2]), "+f"(c[3])
                        : "r"(ah[mt][0]), "r"(ah[mt][1]), "r"(ah[mt][2]), "r"(ah[mt][3]),
                          "r"(bl0), "r"(bl1));
                    asm volatile("mma.sync.aligned.m16n8k16.row.col.f32.bf16.bf16.f32 "
                        "{%0,%1,%2,%3}, {%4,%5,%6,%7}, {%8,%9}, {%0,%1,%2,%3};"
                        : "+f"(c[0]), "+f"(c[1]), "+f"(c[2]), "+f"(c[3])
                        : "r"(al[mt][0]), "r"(al[mt][1]), "r"(al[mt][2]), "r"(al[mt][3]),
                          "r"(bh0), "r"(bh1));
                }
            }
        }
    }

    #pragma unroll
    for (int mt = 0; mt < 2; mt++) {
        int r0 = m0 + warp_m + mt * 16 + (lane >> 2);
        int r1 = r0 + 8;
        float d0 = (r0 < N_NODES) ? g_dinv[r0] : 0.0f;
        float d1 = (r1 < N_NODES) ? g_dinv[r1] : 0.0f;
        #pragma unroll
        for (int nt = 0; nt < 4; nt++) {
            int cc = warp_n + nt * 8 + (lane & 3) * 2;
            if (r0 < N_NODES) {
                float2 o = make_float2(acc[mt][nt][0] * d0, acc[mt][nt][1] * d0);
                *(float2*)&g_hs2[(size_t)r0 * D_O + cc] = o;
            }
            if (r1 < N_NODES) {
                float2 o = make_float2(acc[mt][nt][2] * d1, acc[mt][nt][3] * d1);
                *(float2*)&g_hs2[(size_t)r1 * D_O + cc] = o;
            }
        }
    }
}

// ---------------- agg2: CSR gather, warp per node, float2 lanes ------------
__global__ void __launch_bounds__(256) agg2_kernel(const float* __restrict__ b2) {
    int w = (blockIdx.x * blockDim.x + threadIdx.x) >> 5;
    int lane = threadIdx.x & 31;
    if (w >= N_NODES) return;
    int start = g_off[w];
    int cnt   = g_cnt[w];
    const float* base = &g_hs2[(size_t)lane * 2];
    float2 acc = *(const float2*)&g_hs2[(size_t)w * D_O + lane * 2];

    for (int b = 0; b < cnt; b += 32) {
        int n = min(32, cnt - b);
        int src = (lane < n) ? g_cse[start + b + lane].x : 0;
        int j = 0;
        for (; j + 4 <= n; j += 4) {
            int s0 = __shfl_sync(0xffffffffu, src, j);
            int s1 = __shfl_sync(0xffffffffu, src, j + 1);
            int s2 = __shfl_sync(0xffffffffu, src, j + 2);
            int s3 = __shfl_sync(0xffffffffu, src, j + 3);
            float2 v0 = *(const float2*)(base + (size_t)s0 * D_O);
            float2 v1 = *(const float2*)(base + (size_t)s1 * D_O);
            float2 v2 = *(const float2*)(base + (size_t)s2 * D_O);
            float2 v3 = *(const float2*)(base + (size_t)s3 * D_O);
            acc.x += (v0.x + v1.x) + (v2.x + v3.x);
            acc.y += (v0.y + v1.y) + (v2.y + v3.y);
        }
        for (; j < n; j++) {
            int s = __shfl_sync(0xffffffffu, src, j);
            float2 v = *(const float2*)(base + (size_t)s * D_O);
            acc.x += v.x; acc.y += v.y;
        }
    }
    float d = g_dinv[w];
    float2 z = make_float2(fmaf(acc.x, d, b2[lane * 2]),
                           fmaf(acc.y, d, b2[lane * 2 + 1]));
    *(float2*)&g_z[(size_t)w * D_O + lane * 2] = z;
}

// ---------------- decode (CSR order): warp per dst node -------------------
__global__ void __launch_bounds__(256) decode_csr_kernel(float* __restrict__ out) {
    int w = (blockIdx.x * blockDim.x + threadIdx.x) >> 5;
    int lane = threadIdx.x & 31;
    if (w >= N_NODES) return;
    int start = g_off[w];
    int cnt   = g_cnt[w];
    if (cnt == 0) return;
    int half = lane >> 4;
    int hl   = lane & 15;

    float4 zc = *(const float4*)&g_z[(size_t)w * D_O + hl * 4];

    for (int b = 0; b < cnt; b += 2) {
        int idx = b + half;
        float s = 0.0f;
        int eid = 0;
        bool ok = (idx < cnt);
        if (ok) {
            int2 se = g_cse[start + idx];
            eid = se.y;
            float4 zr = *(const float4*)&g_z[(size_t)se.x * D_O + hl * 4];
            s = zc.x * zr.x + zc.y * zr.y + zc.z * zr.z + zc.w * zr.w;
        }
        s += __shfl_xor_sync(0xffffffffu, s, 1);
        s += __shfl_xor_sync(0xffffffffu, s, 2);
        s += __shfl_xor_sync(0xffffffffu, s, 4);
        s += __shfl_xor_sync(0xffffffffu, s, 8);
        if (ok && hl == 0) out[eid] = s;
    }
}

// ---------------- launch ----------------
extern "C" void kernel_launch(void* const* d_in, const int* in_sizes, int n_in,
                              void* d_out, int out_size) {
    const float* x  = (const float*)d_in[0];
    const float* W1 = (const float*)d_in[1];
    const float* b1 = (const float*)d_in[2];
    const float* W2 = (const float*)d_in[3];
    const float* b2 = (const float*)d_in[4];
    const int*   ei = (const int*)d_in[5];
    const int E = in_sizes[5] / 2;

    static cudaStream_t s2 = nullptr;
    static cudaEvent_t evFork = nullptr, evDinv = nullptr, evCsr = nullptr;
    if (!s2) {
        cudaStreamCreateWithFlags(&s2, cudaStreamNonBlocking);
        cudaEventCreateWithFlags(&evFork, cudaEventDisableTiming);
        cudaEventCreateWithFlags(&evDinv, cudaEventDisableTiming);
        cudaEventCreateWithFlags(&evCsr,  cudaEventDisableTiming);
        cudaFuncSetAttribute(gemm1_mma_kernel,
                             cudaFuncAttributeMaxDynamicSharedMemorySize, 65536);
    }

    cudaEventRecord(evFork, 0);
    cudaStreamWaitEvent(s2, evFork, 0);

    // weight prep (main) + degree/scan/CSR chain (s2)
    wsplit_kernel<<<144, 256>>>(W1, W2);
    cnt_init_kernel<<<NB1, 256, 0, s2>>>();
    deg_count_kernel<<<(E + 255) / 256, 256, 0, s2>>>(ei + E, E);
    scan1_kernel<<<NB1, 256, 0, s2>>>();
    cudaEventRecord(evDinv, s2);
    scan2_kernel<<<1, 512, 0, s2>>>();

    // gemm1 overlaps the CSR tail
    cudaStreamWaitEvent(0, evDinv, 0);
    gemm1_mma_kernel<<<(N_NODES + 255) / 256, 512, 65536>>>(x);

    scan3b_kernel<<<NB1, 256, 0, s2>>>();
    csr_fill_kernel<<<(E + 255) / 256, 256, 0, s2>>>(ei, E);
    cudaEventRecord(evCsr, s2);

    cudaStreamWaitEvent(0, evCsr, 0);
    agg1_kernel<<<(N_NODES * 32 + 255) / 256, 256>>>();
    gemm2_mma_kernel<<<(N_NODES + 127) / 128, 256>>>(b1);
    agg2_kernel<<<(N_NODES * 32 + 255) / 256, 256>>>(b2);
    decode_csr_kernel<<<(N_NODES * 32 + 255) / 256, 256>>>((float*)d_out);
}